// round 13
// baseline (speedup 1.0000x reference)
#include <cuda_runtime.h>
#include <cuda_bf16.h>
#include <cuda_fp16.h>
#include <math.h>
#include <stddef.h>
#include <stdint.h>

#define N_NODES 50000
#define N_EDGES 800000
#define IN_FEATS 256
#define HD 256          // NUM_HEADS * OUT_FEATS
#define NUM_HEADS 8
#define OUT_FEATS 32
#define NUM_ET 5

// ---------------- scratch (static device globals; no allocation) ----------
__device__ __half g_feat_src[(size_t)N_NODES * HD];         // 25.6 MB (fp16)
__device__ int    g_cnt[(size_t)N_NODES * NUM_ET];          // 1 MB (BSS zero)
__device__ float  g_w[(size_t)N_NODES * NUM_ET * NUM_HEADS];// 8 MB
__device__ int    g_off[N_NODES];
__device__ int    g_deg[N_NODES];
__device__ int    g_cur[N_NODES];
__device__ int    g_csr[N_EDGES];                           // src|t<<16
__device__ int    g_total;

// ---------------- streaming-cache helpers ---------------------------------
__device__ __forceinline__ void stcs4(float* p, float4 v) {
    asm volatile("st.global.cs.v4.f32 [%0], {%1,%2,%3,%4};"
                 :: "l"(p), "f"(v.x), "f"(v.y), "f"(v.z), "f"(v.w) : "memory");
}
__device__ __forceinline__ int ldcs(const int* p) {
    int v;
    asm volatile("ld.global.cs.s32 %0, [%1];" : "=r"(v) : "l"(p));
    return v;
}

// =====================================================================
// 1) GEMM: C[M,256](fp16) = A[M,256]*B[256,256]^T, single-pass tf32 MMA.
//    BM=128, BN=128, BK=32, 256 threads, 8 warps (4Mx2N), warp 32x64.
// =====================================================================
__device__ __forceinline__ void mma_tf32(float* c, const uint32_t* a,
                                         uint32_t b0, uint32_t b1) {
    asm volatile(
        "mma.sync.aligned.m16n8k8.row.col.f32.tf32.tf32.f32 "
        "{%0,%1,%2,%3},{%4,%5,%6,%7},{%8,%9},{%0,%1,%2,%3};\n"
        : "+f"(c[0]), "+f"(c[1]), "+f"(c[2]), "+f"(c[3])
        : "r"(a[0]), "r"(a[1]), "r"(a[2]), "r"(a[3]), "r"(b0), "r"(b1));
}

__device__ __forceinline__ float tf32r(float x) {
    float y;
    asm("cvt.rna.tf32.f32 %0, %1;" : "=f"(y) : "f"(x));
    return y;
}

__device__ __forceinline__ void cvt_store4(float* p, float4 v) {
    p[0] = tf32r(v.x);
    p[1] = tf32r(v.y);
    p[2] = tf32r(v.z);
    p[3] = tf32r(v.w);
}

__global__ __launch_bounds__(256) void gemm_tf32_kernel(
    const float* __restrict__ A, const float* __restrict__ B,
    __half* __restrict__ C, int M) {
    __shared__ float As[128][36];
    __shared__ float Bs[128][36];

    const int tid = threadIdx.x;
    const int m0 = blockIdx.x * 128;
    const int n0 = blockIdx.y * 128;
    const int warp = tid >> 5, lane = tid & 31;
    const int wm0 = (warp >> 1) * 32;
    const int wn0 = (warp & 1) * 64;
    const int g = lane >> 2, tg = lane & 3;

    const int row0 = tid >> 3;
    const int ac4 = (tid & 7) * 4;

    float acc[2][8][4];
#pragma unroll
    for (int i = 0; i < 2; i++)
#pragma unroll
        for (int j = 0; j < 8; j++)
#pragma unroll
            for (int q = 0; q < 4; q++) acc[i][j][q] = 0.f;

    float4 pa[4], pb[4];
#pragma unroll
    for (int r = 0; r < 4; r++) {
        int row = row0 + r * 32;
        pa[r] = make_float4(0.f, 0.f, 0.f, 0.f);
        if (m0 + row < M)
            pa[r] = __ldg((const float4*)(A + (size_t)(m0 + row) * 256 + ac4));
        pb[r] = __ldg((const float4*)(B + (size_t)(n0 + row) * 256 + ac4));
    }

#pragma unroll 1
    for (int k0 = 0; k0 < 256; k0 += 32) {
#pragma unroll
        for (int r = 0; r < 4; r++) {
            int row = row0 + r * 32;
            cvt_store4(&As[row][ac4], pa[r]);
            cvt_store4(&Bs[row][ac4], pb[r]);
        }
        __syncthreads();

        if (k0 + 32 < 256) {
            const int kn = k0 + 32;
#pragma unroll
            for (int r = 0; r < 4; r++) {
                int row = row0 + r * 32;
                if (m0 + row < M)
                    pa[r] = __ldg((const float4*)(A + (size_t)(m0 + row) * 256 + kn + ac4));
                pb[r] = __ldg((const float4*)(B + (size_t)(n0 + row) * 256 + kn + ac4));
            }
        }

#pragma unroll
        for (int kf = 0; kf < 4; kf++) {
            const int kk = kf * 8;
            uint32_t a[2][4], b[8][2];
#pragma unroll
            for (int i = 0; i < 2; i++) {
                int r0 = wm0 + i * 16 + g;
                a[i][0] = *(const uint32_t*)&As[r0][kk + tg];
                a[i][1] = *(const uint32_t*)&As[r0 + 8][kk + tg];
                a[i][2] = *(const uint32_t*)&As[r0][kk + tg + 4];
                a[i][3] = *(const uint32_t*)&As[r0 + 8][kk + tg + 4];
            }
#pragma unroll
            for (int j = 0; j < 8; j++) {
                int c0 = wn0 + j * 8 + g;
                b[j][0] = *(const uint32_t*)&Bs[c0][kk + tg];
                b[j][1] = *(const uint32_t*)&Bs[c0][kk + tg + 4];
            }
#pragma unroll
            for (int i = 0; i < 2; i++)
#pragma unroll
                for (int j = 0; j < 8; j++)
                    mma_tf32(acc[i][j], a[i], b[j][0], b[j][1]);
        }
        __syncthreads();
    }

#pragma unroll
    for (int i = 0; i < 2; i++)
#pragma unroll
        for (int j = 0; j < 8; j++) {
            int m_lo = m0 + wm0 + i * 16 + g;
            int col  = n0 + wn0 + j * 8 + tg * 2;
            if (m_lo < M)
                *(__half2*)(C + (size_t)m_lo * 256 + col) =
                    __floats2half2_rn(acc[i][j][0], acc[i][j][1]);
            if (m_lo + 8 < M)
                *(__half2*)(C + (size_t)(m_lo + 8) * 256 + col) =
                    __floats2half2_rn(acc[i][j][2], acc[i][j][3]);
        }
}

// ------ 2) histogram, 4 edges/thread, fire-and-forget REDs ----------------
__global__ void count_kernel(const int* __restrict__ dst,
                             const int* __restrict__ ef) {
    int t4 = blockIdx.x * blockDim.x + threadIdx.x;
    if (t4 == 0) g_total = 0;
    int e = t4 * 4;
    if (e + 4 <= N_EDGES) {
        int4 d = __ldg((const int4*)(dst + e));
        int4 t = __ldg((const int4*)(ef + e));
        atomicAdd(&g_cnt[(size_t)d.x * NUM_ET + t.x], 1);
        atomicAdd(&g_cnt[(size_t)d.y * NUM_ET + t.y], 1);
        atomicAdd(&g_cnt[(size_t)d.z * NUM_ET + t.z], 1);
        atomicAdd(&g_cnt[(size_t)d.w * NUM_ET + t.w], 1);
    } else {
        for (; e < N_EDGES; e++)
            atomicAdd(&g_cnt[(size_t)dst[e] * NUM_ET + ef[e]], 1);
    }
}

// ------- 3) fused CSR offsets + softmax (expf hoisted to smem) -------------
__global__ void offsets_softmax_kernel(const float* __restrict__ emb) {
    __shared__ float sE[NUM_ET * NUM_HEADS];
    if (threadIdx.x < NUM_ET * NUM_HEADS)
        sE[threadIdx.x] = expf(__ldg(emb + threadIdx.x));
    __syncthreads();

    int n = blockIdx.x * blockDim.x + threadIdx.x;
    int lane = threadIdx.x & 31;

    int c[NUM_ET];
    int deg = 0;
    if (n < N_NODES) {
#pragma unroll
        for (int t = 0; t < NUM_ET; t++) {
            c[t] = g_cnt[(size_t)n * NUM_ET + t];
            deg += c[t];
        }
#pragma unroll
        for (int t = 0; t < NUM_ET; t++)
            g_cnt[(size_t)n * NUM_ET + t] = 0;   // restore for next replay
    }
    int incl = deg;
#pragma unroll
    for (int o = 1; o < 32; o <<= 1) {
        int v = __shfl_up_sync(0xffffffffu, incl, o);
        if (lane >= o) incl += v;
    }
    int total = __shfl_sync(0xffffffffu, incl, 31);
    int base = 0;
    if (lane == 0) base = atomicAdd(&g_total, total);
    base = __shfl_sync(0xffffffffu, base, 0);

    if (n < N_NODES) {
        int off = base + incl - deg;
        g_off[n] = off;
        g_cur[n] = off;
        g_deg[n] = deg;

#pragma unroll
        for (int h = 0; h < NUM_HEADS; h++) {
            float denom = 0.f;
#pragma unroll
            for (int t = 0; t < NUM_ET; t++)
                denom += (float)c[t] * sE[t * NUM_HEADS + h];
            float inv = 1.f / denom;   // inf only for deg==0 nodes (unread)
#pragma unroll
            for (int t = 0; t < NUM_ET; t++)
                g_w[((size_t)n * NUM_ET + t) * NUM_HEADS + h] =
                    sE[t * NUM_HEADS + h] * inv;
        }
    }
}

// ---------------- 4) scatter edges into CSR, 2 edges/thread ---------------
__global__ void scatter_csr_kernel(const int* __restrict__ src,
                                   const int* __restrict__ dst,
                                   const int* __restrict__ ef) {
    int t2 = blockIdx.x * blockDim.x + threadIdx.x;
    int e = t2 * 2;
    if (e + 2 <= N_EDGES) {
        int2 s = __ldg((const int2*)(src + e));
        int2 d = __ldg((const int2*)(dst + e));
        int2 t = __ldg((const int2*)(ef + e));
        int p0 = atomicAdd(&g_cur[d.x], 1);
        int p1 = atomicAdd(&g_cur[d.y], 1);
        g_csr[p0] = s.x | (t.x << 16);
        g_csr[p1] = s.y | (t.y << 16);
    } else {
        for (; e < N_EDGES; e++) {
            int pos = atomicAdd(&g_cur[dst[e]], 1);
            g_csr[pos] = src[e] | (ef[e] << 16);
        }
    }
}

// ---------------- 4b) attn output, streaming stores ------------------------
__global__ void attn_kernel(const int* __restrict__ dst,
                            const int* __restrict__ ef,
                            float* __restrict__ attn_out) {
    int e = blockIdx.x * blockDim.x + threadIdx.x;
    if (e >= N_EDGES) return;
    int d = __ldg(dst + e);
    int t = __ldg(ef + e);
    const float4* w4 = (const float4*)(g_w + ((size_t)d * NUM_ET + t) * NUM_HEADS);
    float4 w0 = __ldg(w4);
    float4 w1 = __ldg(w4 + 1);
    float* ao = attn_out + (size_t)e * NUM_HEADS;
    stcs4(ao, w0);
    stcs4(ao + 4, w1);
}

// ------- 5) CSR aggregation, pure gather; streaming CSR-in / rst-out -------
__global__ __launch_bounds__(256) void agg_csr_kernel(float* __restrict__ rst) {
    __shared__ float sw[8][NUM_ET * NUM_HEADS];
    const int warp = threadIdx.x >> 5;
    const int lane = threadIdx.x & 31;
    const int d = blockIdx.x * 8 + warp;
    if (d >= N_NODES) return;

    sw[warp][lane] = g_w[(size_t)d * 40 + lane];
    if (lane < 8) sw[warp][32 + lane] = g_w[(size_t)d * 40 + 32 + lane];
    __syncwarp();

    const int off = g_off[d];
    const int deg = g_deg[d];
    const int h0 = lane >> 2;
    const uint4* base = (const uint4*)g_feat_src;

    float acc[8];
#pragma unroll
    for (int q = 0; q < 8; q++) acc[q] = 0.f;

    int i = 0;
    for (; i + 8 <= deg; i += 8) {
        int qq[8];
        uint4 vv[8];
        float ww[8];
#pragma unroll
        for (int u = 0; u < 8; u++) qq[u] = ldcs(&g_csr[off + i + u]);
#pragma unroll
        for (int u = 0; u < 8; u++)
            vv[u] = __ldg(base + (size_t)(qq[u] & 0xFFFF) * 32 + lane);
#pragma unroll
        for (int u = 0; u < 8; u++) ww[u] = sw[warp][(qq[u] >> 16) * 8 + h0];
#pragma unroll
        for (int u = 0; u < 8; u++) {
            const uint32_t* uv = &vv[u].x;
#pragma unroll
            for (int q = 0; q < 4; q++) {
                float2 f = __half22float2(*(const __half2*)&uv[q]);
                acc[q * 2]     += ww[u] * f.x;
                acc[q * 2 + 1] += ww[u] * f.y;
            }
        }
    }
    for (; i + 4 <= deg; i += 4) {
        int qq[4];
        uint4 vv[4];
#pragma unroll
        for (int u = 0; u < 4; u++) qq[u] = ldcs(&g_csr[off + i + u]);
#pragma unroll
        for (int u = 0; u < 4; u++)
            vv[u] = __ldg(base + (size_t)(qq[u] & 0xFFFF) * 32 + lane);
#pragma unroll
        for (int u = 0; u < 4; u++) {
            float w = sw[warp][(qq[u] >> 16) * 8 + h0];
            const uint32_t* uv = &vv[u].x;
#pragma unroll
            for (int q = 0; q < 4; q++) {
                float2 f = __half22float2(*(const __half2*)&uv[q]);
                acc[q * 2]     += w * f.x;
                acc[q * 2 + 1] += w * f.y;
            }
        }
    }
    for (; i < deg; i++) {
        int q0 = ldcs(&g_csr[off + i]);
        uint4 v0 = __ldg(base + (size_t)(q0 & 0xFFFF) * 32 + lane);
        float w0 = sw[warp][(q0 >> 16) * 8 + h0];
        const uint32_t* u0 = &v0.x;
#pragma unroll
        for (int q = 0; q < 4; q++) {
            float2 f0 = __half22float2(*(const __half2*)&u0[q]);
            acc[q * 2]     += w0 * f0.x;
            acc[q * 2 + 1] += w0 * f0.y;
        }
    }

    // streaming stores: don't pollute L2 (keep feat_src resident)
    float* out = rst + (size_t)d * HD + lane * 8;
    stcs4(out,     make_float4(acc[0], acc[1], acc[2], acc[3]));
    stcs4(out + 4, make_float4(acc[4], acc[5], acc[6], acc[7]));
}

// ---------------- launch ---------------------------------------------------
extern "C" void kernel_launch(void* const* d_in, const int* in_sizes, int n_in,
                              void* d_out, int out_size) {
    const float* feat   = (const float*)d_in[0];   // [N, 256]
    const float* fc_w   = (const float*)d_in[1];   // [256, 256]
    const float* emb    = (const float*)d_in[2];   // [5, 8]
    const int*   e_feat = (const int*)d_in[3];     // [E]
    const int*   src    = (const int*)d_in[4];     // [E]
    const int*   dst    = (const int*)d_in[5];     // [E]

    float* out_rst  = (float*)d_out;                           // [N, 8, 32]
    float* out_attn = (float*)d_out + (size_t)N_NODES * HD;    // [E, 8]

    // one-time host-side resources (created on the uncaptured correctness call)
    static cudaStream_t s2 = nullptr, s3 = nullptr;
    static cudaEvent_t evFork = nullptr, evJoin = nullptr;
    static cudaEvent_t evOff = nullptr, evAttn = nullptr;
    if (!s2) {
        cudaStreamCreateWithFlags(&s2, cudaStreamNonBlocking);
        cudaStreamCreateWithFlags(&s3, cudaStreamNonBlocking);
        cudaEventCreateWithFlags(&evFork, cudaEventDisableTiming);
        cudaEventCreateWithFlags(&evJoin, cudaEventDisableTiming);
        cudaEventCreateWithFlags(&evOff,  cudaEventDisableTiming);
        cudaEventCreateWithFlags(&evAttn, cudaEventDisableTiming);
    }

    void* fs_ptr = nullptr;
    cudaGetSymbolAddress(&fs_ptr, g_feat_src);

    // fork: edge pipeline on s2, concurrent with GEMM on main
    cudaEventRecord(evFork, 0);
    cudaStreamWaitEvent(s2, evFork, 0);

    // ---- main stream: GEMM (tensor cores, tf32 single pass) ----
    {
        dim3 grid((N_NODES + 127) / 128, HD / 128);
        gemm_tf32_kernel<<<grid, 256>>>(feat, fc_w, (__half*)fs_ptr, N_NODES);
    }

    // ---- s2: edge pipeline ----
    count_kernel<<<(N_EDGES / 4 + 255) / 256, 256, 0, s2>>>(dst, e_feat);
    offsets_softmax_kernel<<<(N_NODES + 255) / 256, 256, 0, s2>>>(emb);
    cudaEventRecord(evOff, s2);                        // g_w ready
    scatter_csr_kernel<<<(N_EDGES / 2 + 255) / 256, 256, 0, s2>>>(src, dst, e_feat);
    cudaEventRecord(evJoin, s2);

    // ---- s3: attn output, concurrent with agg ----
    cudaStreamWaitEvent(s3, evOff, 0);
    attn_kernel<<<(N_EDGES + 255) / 256, 256, 0, s3>>>(dst, e_feat, out_attn);
    cudaEventRecord(evAttn, s3);

    // ---- main stream: aggregation (needs GEMM + CSR) ----
    cudaStreamWaitEvent(0, evJoin, 0);
    agg_csr_kernel<<<(N_NODES + 7) / 8, 256>>>(out_rst);

    // join attn back to main before capture ends
    cudaStreamWaitEvent(0, evAttn, 0);
}

// round 14
// speedup vs baseline: 1.0164x; 1.0164x over previous
#include <cuda_runtime.h>
#include <cuda_bf16.h>
#include <cuda_fp16.h>
#include <math.h>
#include <stddef.h>
#include <stdint.h>

#define N_NODES 50000
#define N_EDGES 800000
#define IN_FEATS 256
#define HD 256          // NUM_HEADS * OUT_FEATS
#define NUM_HEADS 8
#define OUT_FEATS 32
#define NUM_ET 5
#define CUR_STRIDE 32   // 1 counter per 128B L2 line (anti-serialization pad)

// ---------------- scratch (static device globals; no allocation) ----------
__device__ __half g_feat_src[(size_t)N_NODES * HD];         // 25.6 MB (fp16)
__device__ int    g_cnt[(size_t)N_NODES * NUM_ET];          // 1 MB (BSS zero)
__device__ float  g_w[(size_t)N_NODES * NUM_ET * NUM_HEADS];// 8 MB
__device__ int    g_off[N_NODES];
__device__ int    g_deg[N_NODES];
__device__ int    g_cur[(size_t)N_NODES * CUR_STRIDE];      // 6.4 MB, padded
__device__ int    g_csr[N_EDGES];                           // src|t<<16
__device__ int    g_total;

// =====================================================================
// 1) GEMM: C[M,256](fp16) = A[M,256]*B[256,256]^T, single-pass tf32 MMA.
//    BM=128, BN=128, BK=32, 256 threads, 8 warps (4Mx2N), warp 32x64.
// =====================================================================
__device__ __forceinline__ void mma_tf32(float* c, const uint32_t* a,
                                         uint32_t b0, uint32_t b1) {
    asm volatile(
        "mma.sync.aligned.m16n8k8.row.col.f32.tf32.tf32.f32 "
        "{%0,%1,%2,%3},{%4,%5,%6,%7},{%8,%9},{%0,%1,%2,%3};\n"
        : "+f"(c[0]), "+f"(c[1]), "+f"(c[2]), "+f"(c[3])
        : "r"(a[0]), "r"(a[1]), "r"(a[2]), "r"(a[3]), "r"(b0), "r"(b1));
}

__device__ __forceinline__ float tf32r(float x) {
    float y;
    asm("cvt.rna.tf32.f32 %0, %1;" : "=f"(y) : "f"(x));
    return y;
}

__device__ __forceinline__ void cvt_store4(float* p, float4 v) {
    p[0] = tf32r(v.x);
    p[1] = tf32r(v.y);
    p[2] = tf32r(v.z);
    p[3] = tf32r(v.w);
}

__global__ __launch_bounds__(256) void gemm_tf32_kernel(
    const float* __restrict__ A, const float* __restrict__ B,
    __half* __restrict__ C, int M) {
    __shared__ float As[128][36];
    __shared__ float Bs[128][36];

    const int tid = threadIdx.x;
    const int m0 = blockIdx.x * 128;
    const int n0 = blockIdx.y * 128;
    const int warp = tid >> 5, lane = tid & 31;
    const int wm0 = (warp >> 1) * 32;
    const int wn0 = (warp & 1) * 64;
    const int g = lane >> 2, tg = lane & 3;

    const int row0 = tid >> 3;
    const int ac4 = (tid & 7) * 4;

    float acc[2][8][4];
#pragma unroll
    for (int i = 0; i < 2; i++)
#pragma unroll
        for (int j = 0; j < 8; j++)
#pragma unroll
            for (int q = 0; q < 4; q++) acc[i][j][q] = 0.f;

    float4 pa[4], pb[4];
#pragma unroll
    for (int r = 0; r < 4; r++) {
        int row = row0 + r * 32;
        pa[r] = make_float4(0.f, 0.f, 0.f, 0.f);
        if (m0 + row < M)
            pa[r] = __ldg((const float4*)(A + (size_t)(m0 + row) * 256 + ac4));
        pb[r] = __ldg((const float4*)(B + (size_t)(n0 + row) * 256 + ac4));
    }

#pragma unroll 1
    for (int k0 = 0; k0 < 256; k0 += 32) {
#pragma unroll
        for (int r = 0; r < 4; r++) {
            int row = row0 + r * 32;
            cvt_store4(&As[row][ac4], pa[r]);
            cvt_store4(&Bs[row][ac4], pb[r]);
        }
        __syncthreads();

        if (k0 + 32 < 256) {
            const int kn = k0 + 32;
#pragma unroll
            for (int r = 0; r < 4; r++) {
                int row = row0 + r * 32;
                if (m0 + row < M)
                    pa[r] = __ldg((const float4*)(A + (size_t)(m0 + row) * 256 + kn + ac4));
                pb[r] = __ldg((const float4*)(B + (size_t)(n0 + row) * 256 + kn + ac4));
            }
        }

#pragma unroll
        for (int kf = 0; kf < 4; kf++) {
            const int kk = kf * 8;
            uint32_t a[2][4], b[8][2];
#pragma unroll
            for (int i = 0; i < 2; i++) {
                int r0 = wm0 + i * 16 + g;
                a[i][0] = *(const uint32_t*)&As[r0][kk + tg];
                a[i][1] = *(const uint32_t*)&As[r0 + 8][kk + tg];
                a[i][2] = *(const uint32_t*)&As[r0][kk + tg + 4];
                a[i][3] = *(const uint32_t*)&As[r0 + 8][kk + tg + 4];
            }
#pragma unroll
            for (int j = 0; j < 8; j++) {
                int c0 = wn0 + j * 8 + g;
                b[j][0] = *(const uint32_t*)&Bs[c0][kk + tg];
                b[j][1] = *(const uint32_t*)&Bs[c0][kk + tg + 4];
            }
#pragma unroll
            for (int i = 0; i < 2; i++)
#pragma unroll
                for (int j = 0; j < 8; j++)
                    mma_tf32(acc[i][j], a[i], b[j][0], b[j][1]);
        }
        __syncthreads();
    }

#pragma unroll
    for (int i = 0; i < 2; i++)
#pragma unroll
        for (int j = 0; j < 8; j++) {
            int m_lo = m0 + wm0 + i * 16 + g;
            int col  = n0 + wn0 + j * 8 + tg * 2;
            if (m_lo < M)
                *(__half2*)(C + (size_t)m_lo * 256 + col) =
                    __floats2half2_rn(acc[i][j][0], acc[i][j][1]);
            if (m_lo + 8 < M)
                *(__half2*)(C + (size_t)(m_lo + 8) * 256 + col) =
                    __floats2half2_rn(acc[i][j][2], acc[i][j][3]);
        }
}

// ------ 2) histogram, 4 edges/thread, fire-and-forget REDs ----------------
__global__ void count_kernel(const int* __restrict__ dst,
                             const int* __restrict__ ef) {
    int t4 = blockIdx.x * blockDim.x + threadIdx.x;
    if (t4 == 0) g_total = 0;
    int e = t4 * 4;
    if (e + 4 <= N_EDGES) {
        int4 d = __ldg((const int4*)(dst + e));
        int4 t = __ldg((const int4*)(ef + e));
        atomicAdd(&g_cnt[(size_t)d.x * NUM_ET + t.x], 1);
        atomicAdd(&g_cnt[(size_t)d.y * NUM_ET + t.y], 1);
        atomicAdd(&g_cnt[(size_t)d.z * NUM_ET + t.z], 1);
        atomicAdd(&g_cnt[(size_t)d.w * NUM_ET + t.w], 1);
    } else {
        for (; e < N_EDGES; e++)
            atomicAdd(&g_cnt[(size_t)dst[e] * NUM_ET + ef[e]], 1);
    }
}

// ------- 3) fused CSR offsets + softmax (expf hoisted to smem) -------------
__global__ void offsets_softmax_kernel(const float* __restrict__ emb) {
    __shared__ float sE[NUM_ET * NUM_HEADS];
    if (threadIdx.x < NUM_ET * NUM_HEADS)
        sE[threadIdx.x] = expf(__ldg(emb + threadIdx.x));
    __syncthreads();

    int n = blockIdx.x * blockDim.x + threadIdx.x;
    int lane = threadIdx.x & 31;

    int c[NUM_ET];
    int deg = 0;
    if (n < N_NODES) {
#pragma unroll
        for (int t = 0; t < NUM_ET; t++) {
            c[t] = g_cnt[(size_t)n * NUM_ET + t];
            deg += c[t];
        }
#pragma unroll
        for (int t = 0; t < NUM_ET; t++)
            g_cnt[(size_t)n * NUM_ET + t] = 0;   // restore for next replay
    }
    int incl = deg;
#pragma unroll
    for (int o = 1; o < 32; o <<= 1) {
        int v = __shfl_up_sync(0xffffffffu, incl, o);
        if (lane >= o) incl += v;
    }
    int total = __shfl_sync(0xffffffffu, incl, 31);
    int base = 0;
    if (lane == 0) base = atomicAdd(&g_total, total);
    base = __shfl_sync(0xffffffffu, base, 0);

    if (n < N_NODES) {
        int off = base + incl - deg;
        g_off[n] = off;
        g_cur[(size_t)n * CUR_STRIDE] = off;   // padded: 1 counter / 128B line
        g_deg[n] = deg;

#pragma unroll
        for (int h = 0; h < NUM_HEADS; h++) {
            float denom = 0.f;
#pragma unroll
            for (int t = 0; t < NUM_ET; t++)
                denom += (float)c[t] * sE[t * NUM_HEADS + h];
            float inv = 1.f / denom;   // inf only for deg==0 nodes (unread)
#pragma unroll
            for (int t = 0; t < NUM_ET; t++)
                g_w[((size_t)n * NUM_ET + t) * NUM_HEADS + h] =
                    sE[t * NUM_HEADS + h] * inv;
        }
    }
}

// ---------------- 4) scatter edges into CSR (slim), 1 edge/thread ---------
__global__ void scatter_csr_kernel(const int* __restrict__ src,
                                   const int* __restrict__ dst,
                                   const int* __restrict__ ef) {
    int e = blockIdx.x * blockDim.x + threadIdx.x;
    if (e >= N_EDGES) return;
    int s = src[e];
    int d = dst[e];
    int t = ef[e];
    int pos = atomicAdd(&g_cur[(size_t)d * CUR_STRIDE], 1);
    g_csr[pos] = s | (t << 16);
}

// ---------------- 4b) attn output, 1 thread/edge, coalesced writes --------
__global__ void attn_kernel(const int* __restrict__ dst,
                            const int* __restrict__ ef,
                            float* __restrict__ attn_out) {
    int e = blockIdx.x * blockDim.x + threadIdx.x;
    if (e >= N_EDGES) return;
    int d = __ldg(dst + e);
    int t = __ldg(ef + e);
    const float4* w4 = (const float4*)(g_w + ((size_t)d * NUM_ET + t) * NUM_HEADS);
    float4 w0 = __ldg(w4);
    float4 w1 = __ldg(w4 + 1);
    float4* ao = (float4*)(attn_out + (size_t)e * NUM_HEADS);
    ao[0] = w0;
    ao[1] = w1;
}

// ---------------- 5) CSR aggregation, pure gather (8-deep MLP) -------------
__global__ __launch_bounds__(256) void agg_csr_kernel(float* __restrict__ rst) {
    __shared__ float sw[8][NUM_ET * NUM_HEADS];
    const int warp = threadIdx.x >> 5;
    const int lane = threadIdx.x & 31;
    const int d = blockIdx.x * 8 + warp;
    if (d >= N_NODES) return;

    sw[warp][lane] = g_w[(size_t)d * 40 + lane];
    if (lane < 8) sw[warp][32 + lane] = g_w[(size_t)d * 40 + 32 + lane];
    __syncwarp();

    const int off = g_off[d];
    const int deg = g_deg[d];
    const int h0 = lane >> 2;
    const uint4* base = (const uint4*)g_feat_src;

    float acc[8];
#pragma unroll
    for (int q = 0; q < 8; q++) acc[q] = 0.f;

    int i = 0;
    for (; i + 8 <= deg; i += 8) {
        int qq[8];
        uint4 vv[8];
        float ww[8];
#pragma unroll
        for (int u = 0; u < 8; u++) qq[u] = g_csr[off + i + u];
#pragma unroll
        for (int u = 0; u < 8; u++)
            vv[u] = __ldg(base + (size_t)(qq[u] & 0xFFFF) * 32 + lane);
#pragma unroll
        for (int u = 0; u < 8; u++) ww[u] = sw[warp][(qq[u] >> 16) * 8 + h0];
#pragma unroll
        for (int u = 0; u < 8; u++) {
            const uint32_t* uv = &vv[u].x;
#pragma unroll
            for (int q = 0; q < 4; q++) {
                float2 f = __half22float2(*(const __half2*)&uv[q]);
                acc[q * 2]     += ww[u] * f.x;
                acc[q * 2 + 1] += ww[u] * f.y;
            }
        }
    }
    for (; i + 4 <= deg; i += 4) {
        int qq[4];
        uint4 vv[4];
#pragma unroll
        for (int u = 0; u < 4; u++) qq[u] = g_csr[off + i + u];
#pragma unroll
        for (int u = 0; u < 4; u++)
            vv[u] = __ldg(base + (size_t)(qq[u] & 0xFFFF) * 32 + lane);
#pragma unroll
        for (int u = 0; u < 4; u++) {
            float w = sw[warp][(qq[u] >> 16) * 8 + h0];
            const uint32_t* uv = &vv[u].x;
#pragma unroll
            for (int q = 0; q < 4; q++) {
                float2 f = __half22float2(*(const __half2*)&uv[q]);
                acc[q * 2]     += w * f.x;
                acc[q * 2 + 1] += w * f.y;
            }
        }
    }
    for (; i < deg; i++) {
        int q0 = g_csr[off + i];
        uint4 v0 = __ldg(base + (size_t)(q0 & 0xFFFF) * 32 + lane);
        float w0 = sw[warp][(q0 >> 16) * 8 + h0];
        const uint32_t* u0 = &v0.x;
#pragma unroll
        for (int q = 0; q < 4; q++) {
            float2 f0 = __half22float2(*(const __half2*)&u0[q]);
            acc[q * 2]     += w0 * f0.x;
            acc[q * 2 + 1] += w0 * f0.y;
        }
    }

    float4* out = (float4*)(rst + (size_t)d * HD) + lane * 2;
    out[0] = make_float4(acc[0], acc[1], acc[2], acc[3]);
    out[1] = make_float4(acc[4], acc[5], acc[6], acc[7]);
}

// ---------------- launch ---------------------------------------------------
extern "C" void kernel_launch(void* const* d_in, const int* in_sizes, int n_in,
                              void* d_out, int out_size) {
    const float* feat   = (const float*)d_in[0];   // [N, 256]
    const float* fc_w   = (const float*)d_in[1];   // [256, 256]
    const float* emb    = (const float*)d_in[2];   // [5, 8]
    const int*   e_feat = (const int*)d_in[3];     // [E]
    const int*   src    = (const int*)d_in[4];     // [E]
    const int*   dst    = (const int*)d_in[5];     // [E]

    float* out_rst  = (float*)d_out;                           // [N, 8, 32]
    float* out_attn = (float*)d_out + (size_t)N_NODES * HD;    // [E, 8]

    // one-time host-side resources (created on the uncaptured correctness call)
    static cudaStream_t s2 = nullptr, s3 = nullptr;
    static cudaEvent_t evFork = nullptr, evJoin = nullptr;
    static cudaEvent_t evOff = nullptr, evAttn = nullptr;
    if (!s2) {
        cudaStreamCreateWithFlags(&s2, cudaStreamNonBlocking);
        cudaStreamCreateWithFlags(&s3, cudaStreamNonBlocking);
        cudaEventCreateWithFlags(&evFork, cudaEventDisableTiming);
        cudaEventCreateWithFlags(&evJoin, cudaEventDisableTiming);
        cudaEventCreateWithFlags(&evOff,  cudaEventDisableTiming);
        cudaEventCreateWithFlags(&evAttn, cudaEventDisableTiming);
    }

    void* fs_ptr = nullptr;
    cudaGetSymbolAddress(&fs_ptr, g_feat_src);

    // fork: edge pipeline on s2, concurrent with GEMM on main
    cudaEventRecord(evFork, 0);
    cudaStreamWaitEvent(s2, evFork, 0);

    // ---- main stream: GEMM (tensor cores, tf32 single pass) ----
    {
        dim3 grid((N_NODES + 127) / 128, HD / 128);
        gemm_tf32_kernel<<<grid, 256>>>(feat, fc_w, (__half*)fs_ptr, N_NODES);
    }

    // ---- s2: edge pipeline ----
    count_kernel<<<(N_EDGES / 4 + 255) / 256, 256, 0, s2>>>(dst, e_feat);
    offsets_softmax_kernel<<<(N_NODES + 255) / 256, 256, 0, s2>>>(emb);
    cudaEventRecord(evOff, s2);                        // g_w ready
    scatter_csr_kernel<<<(N_EDGES + 255) / 256, 256, 0, s2>>>(src, dst, e_feat);
    cudaEventRecord(evJoin, s2);

    // ---- s3: attn output, concurrent with agg ----
    cudaStreamWaitEvent(s3, evOff, 0);
    attn_kernel<<<(N_EDGES + 255) / 256, 256, 0, s3>>>(dst, e_feat, out_attn);
    cudaEventRecord(evAttn, s3);

    // ---- main stream: aggregation (needs GEMM + CSR) ----
    cudaStreamWaitEvent(0, evJoin, 0);
    agg_csr_kernel<<<(N_NODES + 7) / 8, 256>>>(out_rst);

    // join attn back to main before capture ends
    cudaStreamWaitEvent(0, evAttn, 0);
}

// round 15
// speedup vs baseline: 1.0166x; 1.0003x over previous
#include <cuda_runtime.h>
#include <cuda_bf16.h>
#include <cuda_fp16.h>
#include <math.h>
#include <stddef.h>
#include <stdint.h>

#define N_NODES 50000
#define N_EDGES 800000
#define IN_FEATS 256
#define HD 256          // NUM_HEADS * OUT_FEATS
#define NUM_HEADS 8
#define OUT_FEATS 32
#define NUM_ET 5
#define CUR_STRIDE 32   // 1 counter per 128B L2 line

// ---------------- scratch (static device globals; no allocation) ----------
__device__ __half g_feat_src[(size_t)N_NODES * HD];         // 25.6 MB (fp16)
__device__ int    g_cnt[(size_t)N_NODES * NUM_ET];          // 1 MB (BSS zero)
__device__ float  g_w[(size_t)N_NODES * NUM_ET * NUM_HEADS];// 8 MB
__device__ int    g_off[N_NODES];
__device__ int    g_deg[N_NODES];
__device__ int    g_cur[(size_t)N_NODES * CUR_STRIDE];      // 6.4 MB, padded
__device__ int    g_csr[N_EDGES];                           // src|t<<16
__device__ int    g_total;

// =====================================================================
// 1) GEMM: C[M,256](fp16) = A[M,256]*B[256,256]^T, single-pass tf32 MMA.
//    BM=128, BN=128, BK=32, 256 threads, 8 warps (4Mx2N), warp 32x64.
// =====================================================================
__device__ __forceinline__ void mma_tf32(float* c, const uint32_t* a,
                                         uint32_t b0, uint32_t b1) {
    asm volatile(
        "mma.sync.aligned.m16n8k8.row.col.f32.tf32.tf32.f32 "
        "{%0,%1,%2,%3},{%4,%5,%6,%7},{%8,%9},{%0,%1,%2,%3};\n"
        : "+f"(c[0]), "+f"(c[1]), "+f"(c[2]), "+f"(c[3])
        : "r"(a[0]), "r"(a[1]), "r"(a[2]), "r"(a[3]), "r"(b0), "r"(b1));
}

__device__ __forceinline__ float tf32r(float x) {
    float y;
    asm("cvt.rna.tf32.f32 %0, %1;" : "=f"(y) : "f"(x));
    return y;
}

__device__ __forceinline__ void cvt_store4(float* p, float4 v) {
    p[0] = tf32r(v.x);
    p[1] = tf32r(v.y);
    p[2] = tf32r(v.z);
    p[3] = tf32r(v.w);
}

__global__ __launch_bounds__(256) void gemm_tf32_kernel(
    const float* __restrict__ A, const float* __restrict__ B,
    __half* __restrict__ C, int M) {
    __shared__ float As[128][36];
    __shared__ float Bs[128][36];

    const int tid = threadIdx.x;
    const int m0 = blockIdx.x * 128;
    const int n0 = blockIdx.y * 128;
    const int warp = tid >> 5, lane = tid & 31;
    const int wm0 = (warp >> 1) * 32;
    const int wn0 = (warp & 1) * 64;
    const int g = lane >> 2, tg = lane & 3;

    const int row0 = tid >> 3;
    const int ac4 = (tid & 7) * 4;

    float acc[2][8][4];
#pragma unroll
    for (int i = 0; i < 2; i++)
#pragma unroll
        for (int j = 0; j < 8; j++)
#pragma unroll
            for (int q = 0; q < 4; q++) acc[i][j][q] = 0.f;

    float4 pa[4], pb[4];
#pragma unroll
    for (int r = 0; r < 4; r++) {
        int row = row0 + r * 32;
        pa[r] = make_float4(0.f, 0.f, 0.f, 0.f);
        if (m0 + row < M)
            pa[r] = __ldg((const float4*)(A + (size_t)(m0 + row) * 256 + ac4));
        pb[r] = __ldg((const float4*)(B + (size_t)(n0 + row) * 256 + ac4));
    }

#pragma unroll 1
    for (int k0 = 0; k0 < 256; k0 += 32) {
#pragma unroll
        for (int r = 0; r < 4; r++) {
            int row = row0 + r * 32;
            cvt_store4(&As[row][ac4], pa[r]);
            cvt_store4(&Bs[row][ac4], pb[r]);
        }
        __syncthreads();

        if (k0 + 32 < 256) {
            const int kn = k0 + 32;
#pragma unroll
            for (int r = 0; r < 4; r++) {
                int row = row0 + r * 32;
                if (m0 + row < M)
                    pa[r] = __ldg((const float4*)(A + (size_t)(m0 + row) * 256 + kn + ac4));
                pb[r] = __ldg((const float4*)(B + (size_t)(n0 + row) * 256 + kn + ac4));
            }
        }

#pragma unroll
        for (int kf = 0; kf < 4; kf++) {
            const int kk = kf * 8;
            uint32_t a[2][4], b[8][2];
#pragma unroll
            for (int i = 0; i < 2; i++) {
                int r0 = wm0 + i * 16 + g;
                a[i][0] = *(const uint32_t*)&As[r0][kk + tg];
                a[i][1] = *(const uint32_t*)&As[r0 + 8][kk + tg];
                a[i][2] = *(const uint32_t*)&As[r0][kk + tg + 4];
                a[i][3] = *(const uint32_t*)&As[r0 + 8][kk + tg + 4];
            }
#pragma unroll
            for (int j = 0; j < 8; j++) {
                int c0 = wn0 + j * 8 + g;
                b[j][0] = *(const uint32_t*)&Bs[c0][kk + tg];
                b[j][1] = *(const uint32_t*)&Bs[c0][kk + tg + 4];
            }
#pragma unroll
            for (int i = 0; i < 2; i++)
#pragma unroll
                for (int j = 0; j < 8; j++)
                    mma_tf32(acc[i][j], a[i], b[j][0], b[j][1]);
        }
        __syncthreads();
    }

#pragma unroll
    for (int i = 0; i < 2; i++)
#pragma unroll
        for (int j = 0; j < 8; j++) {
            int m_lo = m0 + wm0 + i * 16 + g;
            int col  = n0 + wn0 + j * 8 + tg * 2;
            if (m_lo < M)
                *(__half2*)(C + (size_t)m_lo * 256 + col) =
                    __floats2half2_rn(acc[i][j][0], acc[i][j][1]);
            if (m_lo + 8 < M)
                *(__half2*)(C + (size_t)(m_lo + 8) * 256 + col) =
                    __floats2half2_rn(acc[i][j][2], acc[i][j][3]);
        }
}

// ------ 2) histogram, 4 edges/thread, fire-and-forget REDs ----------------
__global__ void count_kernel(const int* __restrict__ dst,
                             const int* __restrict__ ef) {
    int t4 = blockIdx.x * blockDim.x + threadIdx.x;
    if (t4 == 0) g_total = 0;
    int e = t4 * 4;
    if (e + 4 <= N_EDGES) {
        int4 d = __ldg((const int4*)(dst + e));
        int4 t = __ldg((const int4*)(ef + e));
        atomicAdd(&g_cnt[(size_t)d.x * NUM_ET + t.x], 1);
        atomicAdd(&g_cnt[(size_t)d.y * NUM_ET + t.y], 1);
        atomicAdd(&g_cnt[(size_t)d.z * NUM_ET + t.z], 1);
        atomicAdd(&g_cnt[(size_t)d.w * NUM_ET + t.w], 1);
    } else {
        for (; e < N_EDGES; e++)
            atomicAdd(&g_cnt[(size_t)dst[e] * NUM_ET + ef[e]], 1);
    }
}

// ------- 3) fused CSR offsets + softmax (expf hoisted to smem) -------------
__global__ void offsets_softmax_kernel(const float* __restrict__ emb) {
    __shared__ float sE[NUM_ET * NUM_HEADS];
    if (threadIdx.x < NUM_ET * NUM_HEADS)
        sE[threadIdx.x] = expf(__ldg(emb + threadIdx.x));
    __syncthreads();

    int n = blockIdx.x * blockDim.x + threadIdx.x;
    int lane = threadIdx.x & 31;

    int c[NUM_ET];
    int deg = 0;
    if (n < N_NODES) {
#pragma unroll
        for (int t = 0; t < NUM_ET; t++) {
            c[t] = g_cnt[(size_t)n * NUM_ET + t];
            deg += c[t];
        }
#pragma unroll
        for (int t = 0; t < NUM_ET; t++)
            g_cnt[(size_t)n * NUM_ET + t] = 0;   // restore for next replay
    }
    int incl = deg;
#pragma unroll
    for (int o = 1; o < 32; o <<= 1) {
        int v = __shfl_up_sync(0xffffffffu, incl, o);
        if (lane >= o) incl += v;
    }
    int total = __shfl_sync(0xffffffffu, incl, 31);
    int base = 0;
    if (lane == 0) base = atomicAdd(&g_total, total);
    base = __shfl_sync(0xffffffffu, base, 0);

    if (n < N_NODES) {
        int off = base + incl - deg;
        g_off[n] = off;
        g_cur[(size_t)n * CUR_STRIDE] = off;
        g_deg[n] = deg;

#pragma unroll
        for (int h = 0; h < NUM_HEADS; h++) {
            float denom = 0.f;
#pragma unroll
            for (int t = 0; t < NUM_ET; t++)
                denom += (float)c[t] * sE[t * NUM_HEADS + h];
            float inv = 1.f / denom;   // inf only for deg==0 nodes (unread)
#pragma unroll
            for (int t = 0; t < NUM_ET; t++)
                g_w[((size_t)n * NUM_ET + t) * NUM_HEADS + h] =
                    sE[t * NUM_HEADS + h] * inv;
        }
    }
}

// ---------------- 4) scatter edges into CSR (slim), 1 edge/thread ---------
__global__ void scatter_csr_kernel(const int* __restrict__ src,
                                   const int* __restrict__ dst,
                                   const int* __restrict__ ef) {
    int e = blockIdx.x * blockDim.x + threadIdx.x;
    if (e >= N_EDGES) return;
    int s = src[e];
    int d = dst[e];
    int t = ef[e];
    int pos = atomicAdd(&g_cur[(size_t)d * CUR_STRIDE], 1);
    g_csr[pos] = s | (t << 16);
}

// ---------------- 4b) attn output, 1 thread/edge, coalesced writes --------
__global__ void attn_kernel(const int* __restrict__ dst,
                            const int* __restrict__ ef,
                            float* __restrict__ attn_out) {
    int e = blockIdx.x * blockDim.x + threadIdx.x;
    if (e >= N_EDGES) return;
    int d = __ldg(dst + e);
    int t = __ldg(ef + e);
    const float4* w4 = (const float4*)(g_w + ((size_t)d * NUM_ET + t) * NUM_HEADS);
    float4 w0 = __ldg(w4);
    float4 w1 = __ldg(w4 + 1);
    float4* ao = (float4*)(attn_out + (size_t)e * NUM_HEADS);
    ao[0] = w0;
    ao[1] = w1;
}

// ---- 5) CSR aggregation: 64-thread CTAs (2 warps = 2 nodes) ---------------
// Small CTA -> slot recycles when just 2 warps finish (vs 8), cutting
// degree-straggler waste while keeping sequential node order + locality.
__global__ __launch_bounds__(64) void agg_csr_kernel(float* __restrict__ rst) {
    __shared__ float sw[2][NUM_ET * NUM_HEADS];
    const int warp = threadIdx.x >> 5;
    const int lane = threadIdx.x & 31;
    const int d = blockIdx.x * 2 + warp;
    if (d >= N_NODES) return;

    sw[warp][lane] = g_w[(size_t)d * 40 + lane];
    if (lane < 8) sw[warp][32 + lane] = g_w[(size_t)d * 40 + 32 + lane];
    __syncwarp();

    const int off = g_off[d];
    const int deg = g_deg[d];
    const int h0 = lane >> 2;
    const uint4* base = (const uint4*)g_feat_src;

    float acc[8];
#pragma unroll
    for (int q = 0; q < 8; q++) acc[q] = 0.f;

    int i = 0;
    for (; i + 8 <= deg; i += 8) {
        int qq[8];
        uint4 vv[8];
        float ww[8];
#pragma unroll
        for (int u = 0; u < 8; u++) qq[u] = g_csr[off + i + u];
#pragma unroll
        for (int u = 0; u < 8; u++)
            vv[u] = __ldg(base + (size_t)(qq[u] & 0xFFFF) * 32 + lane);
#pragma unroll
        for (int u = 0; u < 8; u++) ww[u] = sw[warp][(qq[u] >> 16) * 8 + h0];
#pragma unroll
        for (int u = 0; u < 8; u++) {
            const uint32_t* uv = &vv[u].x;
#pragma unroll
            for (int q = 0; q < 4; q++) {
                float2 f = __half22float2(*(const __half2*)&uv[q]);
                acc[q * 2]     += ww[u] * f.x;
                acc[q * 2 + 1] += ww[u] * f.y;
            }
        }
    }
    for (; i + 4 <= deg; i += 4) {
        int qq[4];
        uint4 vv[4];
#pragma unroll
        for (int u = 0; u < 4; u++) qq[u] = g_csr[off + i + u];
#pragma unroll
        for (int u = 0; u < 4; u++)
            vv[u] = __ldg(base + (size_t)(qq[u] & 0xFFFF) * 32 + lane);
#pragma unroll
        for (int u = 0; u < 4; u++) {
            float w = sw[warp][(qq[u] >> 16) * 8 + h0];
            const uint32_t* uv = &vv[u].x;
#pragma unroll
            for (int q = 0; q < 4; q++) {
                float2 f = __half22float2(*(const __half2*)&uv[q]);
                acc[q * 2]     += w * f.x;
                acc[q * 2 + 1] += w * f.y;
            }
        }
    }
    for (; i < deg; i++) {
        int q0 = g_csr[off + i];
        uint4 v0 = __ldg(base + (size_t)(q0 & 0xFFFF) * 32 + lane);
        float w0 = sw[warp][(q0 >> 16) * 8 + h0];
        const uint32_t* u0 = &v0.x;
#pragma unroll
        for (int q = 0; q < 4; q++) {
            float2 f0 = __half22float2(*(const __half2*)&u0[q]);
            acc[q * 2]     += w0 * f0.x;
            acc[q * 2 + 1] += w0 * f0.y;
        }
    }

    float4* out = (float4*)(rst + (size_t)d * HD) + lane * 2;
    out[0] = make_float4(acc[0], acc[1], acc[2], acc[3]);
    out[1] = make_float4(acc[4], acc[5], acc[6], acc[7]);
}

// ---------------- launch ---------------------------------------------------
extern "C" void kernel_launch(void* const* d_in, const int* in_sizes, int n_in,
                              void* d_out, int out_size) {
    const float* feat   = (const float*)d_in[0];   // [N, 256]
    const float* fc_w   = (const float*)d_in[1];   // [256, 256]
    const float* emb    = (const float*)d_in[2];   // [5, 8]
    const int*   e_feat = (const int*)d_in[3];     // [E]
    const int*   src    = (const int*)d_in[4];     // [E]
    const int*   dst    = (const int*)d_in[5];     // [E]

    float* out_rst  = (float*)d_out;                           // [N, 8, 32]
    float* out_attn = (float*)d_out + (size_t)N_NODES * HD;    // [E, 8]

    // one-time host-side resources (created on the uncaptured correctness call)
    static cudaStream_t s2 = nullptr, s3 = nullptr;
    static cudaEvent_t evFork = nullptr, evJoin = nullptr;
    static cudaEvent_t evOff = nullptr, evAttn = nullptr;
    if (!s2) {
        cudaStreamCreateWithFlags(&s2, cudaStreamNonBlocking);
        cudaStreamCreateWithFlags(&s3, cudaStreamNonBlocking);
        cudaEventCreateWithFlags(&evFork, cudaEventDisableTiming);
        cudaEventCreateWithFlags(&evJoin, cudaEventDisableTiming);
        cudaEventCreateWithFlags(&evOff,  cudaEventDisableTiming);
        cudaEventCreateWithFlags(&evAttn, cudaEventDisableTiming);
    }

    void* fs_ptr = nullptr;
    cudaGetSymbolAddress(&fs_ptr, g_feat_src);

    // fork: edge pipeline on s2, concurrent with GEMM on main
    cudaEventRecord(evFork, 0);
    cudaStreamWaitEvent(s2, evFork, 0);

    // ---- main stream: GEMM (tensor cores, tf32 single pass) ----
    {
        dim3 grid((N_NODES + 127) / 128, HD / 128);
        gemm_tf32_kernel<<<grid, 256>>>(feat, fc_w, (__half*)fs_ptr, N_NODES);
    }

    // ---- s2: edge pipeline ----
    count_kernel<<<(N_EDGES / 4 + 255) / 256, 256, 0, s2>>>(dst, e_feat);
    offsets_softmax_kernel<<<(N_NODES + 255) / 256, 256, 0, s2>>>(emb);
    cudaEventRecord(evOff, s2);                        // g_w ready
    scatter_csr_kernel<<<(N_EDGES + 255) / 256, 256, 0, s2>>>(src, dst, e_feat);
    cudaEventRecord(evJoin, s2);

    // ---- s3: attn output, concurrent with agg ----
    cudaStreamWaitEvent(s3, evOff, 0);
    attn_kernel<<<(N_EDGES + 255) / 256, 256, 0, s3>>>(dst, e_feat, out_attn);
    cudaEventRecord(evAttn, s3);

    // ---- main stream: aggregation (needs GEMM + CSR) ----
    cudaStreamWaitEvent(0, evJoin, 0);
    agg_csr_kernel<<<(N_NODES + 1) / 2, 64>>>(out_rst);

    // join attn back to main before capture ends
    cudaStreamWaitEvent(0, evAttn, 0);
}